// round 17
// baseline (speedup 1.0000x reference)
#include <cuda_runtime.h>
#include <cuda_fp16.h>
#include <cstdint>

#define Bn 16
#define Cc 128
#define Hh 64
#define Ww 64

// ---- scratch: W only ----
// g_wh: W fp16 A-fragment-vector layout, uint4[b][chunk8][tap9][cb8][r8][c4]
__device__ uint4 g_wh[(size_t)Bn * 8 * 9 * 8 * 8 * 4];

__device__ __forceinline__ uint32_t h2(float a, float b) {
    __half2 h = __floats2half2_rn(a, b);
    return *(uint32_t*)&h;
}

// ---- prep: W smem-transpose only. Rows padded to 1164 fl (2-way transpose reads). ----
#define WPREP_P  1164
#define WPREP_P4 291
__global__ void prep_w(const float* __restrict__ w) {
    extern __shared__ float s[];            // [16 co][1164]
    const int b  = blockIdx.x >> 3;
    const int cb = blockIdx.x & 7;
    const float* src = w + ((size_t)b * Cc + cb * 16) * 1152;
#pragma unroll
    for (int it = 0; it < 9; it++) {
        int idx = threadIdx.x + it * 512;   // 4608 uint4
        int row = idx / 288;
        int col = idx - row * 288;
        ((uint4*)s)[row * WPREP_P4 + col] = ((const uint4*)src)[idx];
    }
    __syncthreads();
#pragma unroll
    for (int it = 0; it < 5; it++) {
        int idx = threadIdx.x + it * 512;   // 2304 outputs
        if (idx < 2304) {
            int c    = idx & 3;
            int r    = (idx >> 2) & 7;
            int rest = idx >> 5;
            int t    = rest % 9;
            int ch   = rest / 9;            // 0..7
            int k0   = ch * 16 + 2 * c;
            uint4 o;
            o.x = h2(s[ r      * WPREP_P + (k0    ) * 9 + t], s[ r      * WPREP_P + (k0 + 1) * 9 + t]);
            o.y = h2(s[(r + 8) * WPREP_P + (k0    ) * 9 + t], s[(r + 8) * WPREP_P + (k0 + 1) * 9 + t]);
            o.z = h2(s[ r      * WPREP_P + (k0 + 8) * 9 + t], s[ r      * WPREP_P + (k0 + 9) * 9 + t]);
            o.w = h2(s[(r + 8) * WPREP_P + (k0 + 8) * 9 + t], s[(r + 8) * WPREP_P + (k0 + 9) * 9 + t]);
            g_wh[((((size_t)(b * 8 + ch) * 9 + t) * 8 + cb) * 8 + r) * 4 + c] = o;
        }
    }
}

// ---- main kernel ----
// R14 compute config: CTA = M=64 x N=256 (4 rows x 64 w), 4 warps of 64x64, 2 CTA/SM,
// 8 K-chunks of 16 ci, m16n8k16 fp16.
// NEW X path: cp.async stages the RAW fp32 tile [16 ci][6 rows][64] (single buffer,
// ci stride 392 fl); at chunk top a convert pass (LDS.64 fp32 -> h2 -> STS.128 fp16)
// fills the single fp16 tile [4 pp][6 rows][76 slots][2 u32] (XP=936, XR=152, w=0 at
// slot 4) consumed by the MMA loop. No fp16 X round-trip through DRAM.
#define XP 936
#define XR 152
#define FP16_SZ 3744        // u32 words
#define X32_W   3744        // word offset of fp32 tile
#define X32_CI  392
#define X32_SZ  (16 * 392)  // 6272 words
#define WBASE_B ((FP16_SZ + X32_SZ) * 4)   // 40064 bytes
#define WBUF_U4 1152

__device__ __forceinline__ uint32_t s2u(const void* p) {
    uint32_t a;
    asm("{ .reg .u64 t; cvta.to.shared.u64 t, %1; cvt.u32.u64 %0, t; }" : "=r"(a) : "l"(p));
    return a;
}

#define CP16(dst_u32, src_ptr) \
    asm volatile("cp.async.cg.shared.global [%0], [%1], 16;" :: "r"(dst_u32), "l"(src_ptr))

#define MMA_F16(c, a0, a1, a2, a3, b0v, b1v)                                      \
    asm volatile("mma.sync.aligned.m16n8k16.row.col.f32.f16.f16.f32 "             \
                 "{%0,%1,%2,%3}, {%4,%5,%6,%7}, {%8,%9}, {%0,%1,%2,%3};"          \
                 : "+f"((c)[0]), "+f"((c)[1]), "+f"((c)[2]), "+f"((c)[3])         \
                 : "r"(a0), "r"(a1), "r"(a2), "r"(a3), "r"(b0v), "r"(b1v))

__global__ __launch_bounds__(128, 2)
void resconv_mma(const float* __restrict__ inp, float* __restrict__ out)
{
    extern __shared__ float smf[];
    uint32_t* smu = (uint32_t*)smf;

    const int tid  = threadIdx.x;
    const int lane = tid & 31;
    const int wid  = tid >> 5;       // 0..3 : output row within tile
    const int lr   = lane >> 2;      // 0..7
    const int lc   = lane & 3;       // 0..3

    const int h0  = blockIdx.x * 4;
    const int b   = blockIdx.y;
    const int wmH = blockIdx.z;      // co half of this CTA

    const uint32_t sbase = s2u(smf);
    const uint4* wsrc = g_wh + (size_t)b * 8 * 2304;
    const float* inp_b = inp + (size_t)b * Cc * Hh * Ww;

    // zero fp16 tile (halo slots loop-invariant) + fp32 tile (OOB rows loop-invariant)
    for (int i = tid; i < FP16_SZ + X32_SZ; i += 128) smf[i] = 0.f;
    __syncthreads();

    float acc[4][8][4];
#pragma unroll
    for (int i = 0; i < 4; i++)
#pragma unroll
        for (int j = 0; j < 8; j++)
#pragma unroll
            for (int k = 0; k < 4; k++) acc[i][j][k] = 0.f;

    // cp.async: raw fp32 tile for chunk -> single fp32 buffer
    auto stageX32 = [&](int chunk) {
        const float* src_b = inp_b + (size_t)chunk * 16 * Hh * Ww;
#pragma unroll
        for (int it = 0; it < 12; it++) {
            int idx = tid + it * 128;            // [ci 16][row 6][seg 16] = 1536
            int ci  = idx / 96;
            int rem = idx - ci * 96;
            int row = rem >> 4;
            int seg = rem & 15;
            int gh  = h0 + row - 1;
            if ((unsigned)gh < (unsigned)Hh) {
                const float* src = src_b + ((size_t)ci * Hh + gh) * Ww + seg * 4;
                uint32_t dst = sbase + 4u * (uint32_t)(X32_W + ci * X32_CI + row * 64 + seg * 4);
                CP16(dst, src);
            }
        }
    };
    auto stageW = [&](int chunk, uint32_t woff_b) {
        const uint4* src = wsrc + (size_t)chunk * 2304;
#pragma unroll
        for (int it = 0; it < 9; it++) {
            int idx  = tid + it * 128;           // 0..1151
            int tap  = idx >> 7;
            int rest = idx & 127;
            CP16(sbase + woff_b + idx * 16u, src + tap * 256 + wmH * 128 + rest);
        }
        asm volatile("cp.async.commit_group;" ::: "memory");
    };

    // smem-local convert: fp32 tile -> fp16 pair-interleaved tile (once per byte)
    auto convertX = [&]() {
#pragma unroll
        for (int it = 0; it < 6; it++) {
            int idx = tid + it * 128;            // [pp 4][row 6][seg 32] = 768
            int pp  = idx / 192;
            int rem = idx - pp * 192;
            int row = rem >> 5;
            int seg = rem & 31;
            const float* p0 = smf + X32_W + (2 * pp) * X32_CI + row * 64 + seg * 2;
            float2 f0 = *(const float2*)(p0);                 // ci = 2pp
            float2 f1 = *(const float2*)(p0 +     X32_CI);    // ci = 2pp+1
            float2 f8 = *(const float2*)(p0 + 8 * X32_CI);    // ci = 2pp+8
            float2 f9 = *(const float2*)(p0 + 9 * X32_CI);    // ci = 2pp+9
            uint4 o;
            o.x = h2(f0.x, f1.x);  o.y = h2(f8.x, f9.x);
            o.z = h2(f0.y, f1.y);  o.w = h2(f8.y, f9.y);
            *(uint4*)((char*)smf + 4u * (uint32_t)(pp * XP + row * XR + 8 + seg * 4)) = o;
        }
    };

    stageX32(0);
    stageW(0, WBASE_B);
    asm volatile("cp.async.wait_group 0;" ::: "memory");
    __syncthreads();

    for (int kc = 0; kc < 8; kc++) {
        const int cur = kc & 1;
        const uint4* wbuf = (const uint4*)((const char*)smf + WBASE_B + cur * (WBUF_U4 * 16));

        convertX();              // fp32 tile kc -> fp16 tile
        __syncthreads();         // fp16 ready; fp32 buffer free

        if (kc < 7) {
            stageX32(kc + 1);    // refill fp32 buffer (lands during compute)
            stageW(kc + 1, WBASE_B + (cur ^ 1) * (WBUF_U4 * 16));   // + commit
        }

        const uint32_t* xwarp = smu + lc * XP + wid * XR + (lr + 3) * 2;

#pragma unroll
        for (int t = 0; t < 9; t++) {
            const int kh = t / 3;
            const int kw = t - kh * 3;

            uint4 a[4];
#pragma unroll
            for (int tm = 0; tm < 4; tm++)
                a[tm] = wbuf[t * 128 + tm * 32 + lr * 4 + lc];

            const uint32_t* xq = xwarp + kh * XR + kw * 2;
            uint2 bb[8];
#pragma unroll
            for (int tn = 0; tn < 8; tn++)
                bb[tn] = *(const uint2*)(xq + tn * 16);

#pragma unroll
            for (int tn = 0; tn < 8; tn++)
#pragma unroll
                for (int tm = 0; tm < 4; tm++)
                    MMA_F16(acc[tm][tn], a[tm].x, a[tm].y, a[tm].z, a[tm].w,
                            bb[tn].x, bb[tn].y);
        }

        asm volatile("cp.async.wait_group 0;" ::: "memory");
        __syncthreads();
    }

    // epilogue: out = inp + conv  (this warp: row h0+wid, all 64 w, this co-half)
    const int h = h0 + wid;
#pragma unroll
    for (int tm = 0; tm < 4; tm++) {
#pragma unroll
        for (int tn = 0; tn < 8; tn++) {
            const int w = tn * 8 + lc * 2;
            const int co0 = wmH * 64 + tm * 16 + lr;
#pragma unroll
            for (int half = 0; half < 2; half++) {
                const int co = co0 + half * 8;
                const size_t off = ((size_t)(b * Cc + co) * Hh + h) * Ww + w;
                float2 rv = *(const float2*)(inp + off);
                float2 ov;
                ov.x = rv.x + acc[tm][tn][half * 2 + 0];
                ov.y = rv.y + acc[tm][tn][half * 2 + 1];
                *(float2*)(out + off) = ov;
            }
        }
    }
}

extern "C" void kernel_launch(void* const* d_in, const int* in_sizes, int n_in,
                              void* d_out, int out_size)
{
    const float* inp = (const float*)d_in[0];   // [16,128,64,64]
    const float* wgt = (const float*)d_in[1];   // [16,128,128,3,3]
    float* out = (float*)d_out;

    const int wprep_smem = 16 * WPREP_P * 4;    // 74496
    cudaFuncSetAttribute(prep_w, cudaFuncAttributeMaxDynamicSharedMemorySize, wprep_smem);
    prep_w<<<128, 512, wprep_smem>>>(wgt);

    const int smem_bytes = WBASE_B + 2 * WBUF_U4 * 16;   // 40064 + 36864 = 76928
    cudaFuncSetAttribute(resconv_mma, cudaFuncAttributeMaxDynamicSharedMemorySize, smem_bytes);
    dim3 grid(Hh / 4, Bn, 2);   // (16, 16, 2) = 512 CTAs, 2/SM
    resconv_mma<<<grid, 128, smem_bytes>>>(inp, out);
}